// round 9
// baseline (speedup 1.0000x reference)
#include <cuda_runtime.h>
#include <math.h>

#define NN    100000
#define IN_C  64
#define HID   128
#define OUT_C 64

typedef unsigned long long ull;

// ---------------- scratch (device globals; no allocation allowed) ----------------
__device__ __align__(16) float g_deg[NN];
__device__ __align__(16) float g_agg1[(size_t)NN * IN_C];   // 25.6 MB
__device__ __align__(16) float g_h[(size_t)NN * HID];       // 51.2 MB
__device__ __align__(16) float g_agg2[(size_t)NN * HID];    // 51.2 MB
__device__ int g_is64;

// ---------------- packed f32x2 helpers ----------------
__device__ __forceinline__ ull pack2(float lo, float hi) {
    ull r; asm("mov.b64 %0,{%1,%2};" : "=l"(r) : "f"(lo), "f"(hi)); return r;
}
__device__ __forceinline__ void ffma2(ull& d, ull a, ull b) {
    asm("fma.rn.f32x2 %0,%1,%2,%0;" : "+l"(d) : "l"(a), "l"(b));
}
__device__ __forceinline__ float hadd2(ull v) {
    float lo, hi; asm("mov.b64 {%0,%1},%2;" : "=f"(lo), "=f"(hi) : "l"(v));
    return lo + hi;
}

// ---------------- dtype detect: int64 vs int32 edge_index ----------------
__global__ void detect_kernel(const void* __restrict__ ei) {
    if (blockIdx.x == 0 && threadIdx.x == 0) {
        const unsigned long long* p = (const unsigned long long*)ei;
        int is64 = 1;
#pragma unroll
        for (int i = 0; i < 8; i++)
            if ((p[i] >> 32) != 0ull) is64 = 0;
        g_is64 = is64;
    }
}

// ---------------- zero scratch each launch ----------------
__global__ void zero_kernel() {
    size_t i = (size_t)blockIdx.x * blockDim.x + threadIdx.x;
    size_t stride = (size_t)gridDim.x * blockDim.x;
    float4 z = make_float4(0.f, 0.f, 0.f, 0.f);
    float4* d0 = (float4*)g_deg;
    float4* d1 = (float4*)g_agg1;
    float4* d2 = (float4*)g_agg2;
    for (size_t t = i; t < NN / 4; t += stride) d0[t] = z;
    for (size_t t = i; t < (size_t)NN * IN_C / 4; t += stride) d1[t] = z;
    for (size_t t = i; t < (size_t)NN * HID / 4; t += stride) d2[t] = z;
}

// ---------------- conv1 aggregation: 16 lanes per edge (64 ch) ----------------
__global__ __launch_bounds__(256) void conv1_agg_kernel(
    const float* __restrict__ x, const void* __restrict__ ei, int E)
{
    int tid = blockIdx.x * blockDim.x + threadIdx.x;
    int e = tid >> 4;
    if (e >= E) return;
    int sub = threadIdx.x & 15;
    int is64 = g_is64;
    int src = 0, dst = 0;
    if (sub == 0) {
        if (is64) {
            const long long* p = (const long long*)ei;
            src = (int)p[e]; dst = (int)p[(size_t)E + e];
        } else {
            const int* p = (const int*)ei;
            src = p[e]; dst = p[(size_t)E + e];
        }
    }
    src = __shfl_sync(0xffffffffu, src, 0, 16);
    dst = __shfl_sync(0xffffffffu, dst, 0, 16);

    float4 v = *(const float4*)(x + (size_t)src * IN_C + sub * 4);
    float* d = g_agg1 + (size_t)dst * IN_C + sub * 4;
    asm volatile("red.global.add.v4.f32 [%0], {%1,%2,%3,%4};"
                 :: "l"(d), "f"(v.x), "f"(v.y), "f"(v.z), "f"(v.w) : "memory");
    if (sub == 0) atomicAdd(&g_deg[dst], 1.0f);
}

// ---------------- conv2 aggregation: 32 lanes per edge (128 ch) ----------------
__global__ __launch_bounds__(256) void conv2_agg_kernel(
    const void* __restrict__ ei, int E)
{
    int tid = blockIdx.x * blockDim.x + threadIdx.x;
    int e = tid >> 5;
    if (e >= E) return;
    int ln = threadIdx.x & 31;
    int is64 = g_is64;
    int src = 0, dst = 0;
    if (ln == 0) {
        if (is64) {
            const long long* p = (const long long*)ei;
            src = (int)p[e]; dst = (int)p[(size_t)E + e];
        } else {
            const int* p = (const int*)ei;
            src = p[e]; dst = p[(size_t)E + e];
        }
    }
    src = __shfl_sync(0xffffffffu, src, 0);
    dst = __shfl_sync(0xffffffffu, dst, 0);

    float4 v = *(const float4*)(g_h + (size_t)src * HID + ln * 4);
    float* d = g_agg2 + (size_t)dst * HID + ln * 4;
    asm volatile("red.global.add.v4.f32 [%0], {%1,%2,%3,%4};"
                 :: "l"(d), "f"(v.x), "f"(v.y), "f"(v.z), "f"(v.w) : "memory");
}

// ---------------- conv1 update: h = relu(agg1/deg @ Wl1 + bl1 + x @ Wr1) ----------------
// 128 threads = 128 out channels. Weight columns live in registers as packed
// f32x2 pairs; node data loaded as ulonglong2 (ready-packed). 4 nodes/iter.
__global__ __launch_bounds__(128) void conv1_update_kernel(
    const float* __restrict__ x,
    const float* __restrict__ Wl, const float* __restrict__ bl,
    const float* __restrict__ Wr)
{
    int j = threadIdx.x;                 // out channel 0..127
    ull wl[32], wr[32];
#pragma unroll
    for (int i = 0; i < 32; i++) {
        wl[i] = pack2(__ldg(&Wl[(2 * i) * HID + j]), __ldg(&Wl[(2 * i + 1) * HID + j]));
        wr[i] = pack2(__ldg(&Wr[(2 * i) * HID + j]), __ldg(&Wr[(2 * i + 1) * HID + j]));
    }
    float b = __ldg(&bl[j]);

    for (int g = blockIdx.x; g < NN / 4; g += gridDim.x) {
        int base = g * 4;
        const ulonglong2* ag = (const ulonglong2*)(g_agg1 + (size_t)base * IN_C);
        const ulonglong2* xr = (const ulonglong2*)(x + (size_t)base * IN_C);
        ull al0 = 0, al1 = 0, al2 = 0, al3 = 0;
        ull ar0 = 0, ar1 = 0, ar2 = 0, ar3 = 0;
        // row stride in ulonglong2 units: 64 floats = 16
#pragma unroll
        for (int ks = 0; ks < 16; ks++) {
            ulonglong2 a0 = ag[0 * 16 + ks], a1 = ag[1 * 16 + ks];
            ulonglong2 a2 = ag[2 * 16 + ks], a3 = ag[3 * 16 + ks];
            ulonglong2 x0 = xr[0 * 16 + ks], x1 = xr[1 * 16 + ks];
            ulonglong2 x2 = xr[2 * 16 + ks], x3 = xr[3 * 16 + ks];
            ffma2(al0, a0.x, wl[2 * ks]); ffma2(al0, a0.y, wl[2 * ks + 1]);
            ffma2(al1, a1.x, wl[2 * ks]); ffma2(al1, a1.y, wl[2 * ks + 1]);
            ffma2(al2, a2.x, wl[2 * ks]); ffma2(al2, a2.y, wl[2 * ks + 1]);
            ffma2(al3, a3.x, wl[2 * ks]); ffma2(al3, a3.y, wl[2 * ks + 1]);
            ffma2(ar0, x0.x, wr[2 * ks]); ffma2(ar0, x0.y, wr[2 * ks + 1]);
            ffma2(ar1, x1.x, wr[2 * ks]); ffma2(ar1, x1.y, wr[2 * ks + 1]);
            ffma2(ar2, x2.x, wr[2 * ks]); ffma2(ar2, x2.y, wr[2 * ks + 1]);
            ffma2(ar3, x3.x, wr[2 * ks]); ffma2(ar3, x3.y, wr[2 * ks + 1]);
        }
        float d0 = fmaxf(g_deg[base + 0], 1.f);
        float d1 = fmaxf(g_deg[base + 1], 1.f);
        float d2 = fmaxf(g_deg[base + 2], 1.f);
        float d3 = fmaxf(g_deg[base + 3], 1.f);
        g_h[(size_t)(base + 0) * HID + j] = fmaxf(hadd2(al0) / d0 + b + hadd2(ar0), 0.f);
        g_h[(size_t)(base + 1) * HID + j] = fmaxf(hadd2(al1) / d1 + b + hadd2(ar1), 0.f);
        g_h[(size_t)(base + 2) * HID + j] = fmaxf(hadd2(al2) / d2 + b + hadd2(ar2), 0.f);
        g_h[(size_t)(base + 3) * HID + j] = fmaxf(hadd2(al3) / d3 + b + hadd2(ar3), 0.f);
    }
}

// ---------------- conv2 update: emb = agg2/deg @ Wl2 + bl2 + h @ Wr2 ----------------
// 128 threads: thread j -> channel c=j&63, k-half kh=j>>6 (64 of 128 k each).
// Partials combined through smem; deg division applied after combine.
__global__ __launch_bounds__(128) void conv2_update_kernel(
    const float* __restrict__ Wl, const float* __restrict__ bl,
    const float* __restrict__ Wr, float* __restrict__ emb)
{
    __shared__ float s_al[4][64];
    __shared__ float s_ar[4][64];
    int j = threadIdx.x;
    int c = j & 63;
    int kh = j >> 6;                      // 0 or 1
    int kbase = kh * 64;
    ull wl[32], wr[32];
#pragma unroll
    for (int i = 0; i < 32; i++) {
        wl[i] = pack2(__ldg(&Wl[(kbase + 2 * i) * OUT_C + c]),
                      __ldg(&Wl[(kbase + 2 * i + 1) * OUT_C + c]));
        wr[i] = pack2(__ldg(&Wr[(kbase + 2 * i) * OUT_C + c]),
                      __ldg(&Wr[(kbase + 2 * i + 1) * OUT_C + c]));
    }
    float b = __ldg(&bl[c]);

    for (int g = blockIdx.x; g < NN / 4; g += gridDim.x) {
        int base = g * 4;
        // row stride: 128 floats = 32 ulonglong2; k-half offset = 16
        const ulonglong2* ag = (const ulonglong2*)(g_agg2 + (size_t)base * HID) + kh * 16;
        const ulonglong2* hr = (const ulonglong2*)(g_h + (size_t)base * HID) + kh * 16;
        ull al0 = 0, al1 = 0, al2 = 0, al3 = 0;
        ull ar0 = 0, ar1 = 0, ar2 = 0, ar3 = 0;
#pragma unroll
        for (int ks = 0; ks < 16; ks++) {
            ulonglong2 a0 = ag[0 * 32 + ks], a1 = ag[1 * 32 + ks];
            ulonglong2 a2 = ag[2 * 32 + ks], a3 = ag[3 * 32 + ks];
            ulonglong2 h0 = hr[0 * 32 + ks], h1 = hr[1 * 32 + ks];
            ulonglong2 h2 = hr[2 * 32 + ks], h3 = hr[3 * 32 + ks];
            ffma2(al0, a0.x, wl[2 * ks]); ffma2(al0, a0.y, wl[2 * ks + 1]);
            ffma2(al1, a1.x, wl[2 * ks]); ffma2(al1, a1.y, wl[2 * ks + 1]);
            ffma2(al2, a2.x, wl[2 * ks]); ffma2(al2, a2.y, wl[2 * ks + 1]);
            ffma2(al3, a3.x, wl[2 * ks]); ffma2(al3, a3.y, wl[2 * ks + 1]);
            ffma2(ar0, h0.x, wr[2 * ks]); ffma2(ar0, h0.y, wr[2 * ks + 1]);
            ffma2(ar1, h1.x, wr[2 * ks]); ffma2(ar1, h1.y, wr[2 * ks + 1]);
            ffma2(ar2, h2.x, wr[2 * ks]); ffma2(ar2, h2.y, wr[2 * ks + 1]);
            ffma2(ar3, h3.x, wr[2 * ks]); ffma2(ar3, h3.y, wr[2 * ks + 1]);
        }
        if (kh == 1) {
            s_al[0][c] = hadd2(al0); s_ar[0][c] = hadd2(ar0);
            s_al[1][c] = hadd2(al1); s_ar[1][c] = hadd2(ar1);
            s_al[2][c] = hadd2(al2); s_ar[2][c] = hadd2(ar2);
            s_al[3][c] = hadd2(al3); s_ar[3][c] = hadd2(ar3);
        }
        __syncthreads();
        if (kh == 0) {
            float d0 = fmaxf(g_deg[base + 0], 1.f);
            float d1 = fmaxf(g_deg[base + 1], 1.f);
            float d2 = fmaxf(g_deg[base + 2], 1.f);
            float d3 = fmaxf(g_deg[base + 3], 1.f);
            emb[(size_t)(base + 0) * OUT_C + c] =
                (hadd2(al0) + s_al[0][c]) / d0 + b + hadd2(ar0) + s_ar[0][c];
            emb[(size_t)(base + 1) * OUT_C + c] =
                (hadd2(al1) + s_al[1][c]) / d1 + b + hadd2(ar1) + s_ar[1][c];
            emb[(size_t)(base + 2) * OUT_C + c] =
                (hadd2(al2) + s_al[2][c]) / d2 + b + hadd2(ar2) + s_ar[2][c];
            emb[(size_t)(base + 3) * OUT_C + c] =
                (hadd2(al3) + s_al[3][c]) / d3 + b + hadd2(ar3) + s_ar[3][c];
        }
        __syncthreads();
    }
}

// ---------------- classifier: sigmoid(relu(relu(emb@Wc1+b)@Wc2+b)@Wc3+b) ----------------
// Layer1: thread j = hidden channel (128), packed weights in regs.
// Layer2: thread j -> (c=j&63, kh=j>>6) with k-split + smem combine.
__global__ __launch_bounds__(128) void classifier_kernel(
    const float* __restrict__ emb,
    const float* __restrict__ Wc1, const float* __restrict__ bc1,
    const float* __restrict__ Wc2, const float* __restrict__ bc2,
    const float* __restrict__ Wc3, const float* __restrict__ bc3,
    float* __restrict__ probs)
{
    __shared__ __align__(16) float sc1[4][HID];
    __shared__ float s_p[4][64];
    __shared__ float s_red[2][4];
    int j = threadIdx.x;
    int c = j & 63;
    int kh = j >> 6;
    int kbase = kh * 64;

    ull wc1p[32], wc2p[32];
#pragma unroll
    for (int i = 0; i < 32; i++) {
        wc1p[i] = pack2(__ldg(&Wc1[(2 * i) * HID + j]), __ldg(&Wc1[(2 * i + 1) * HID + j]));
        wc2p[i] = pack2(__ldg(&Wc2[(kbase + 2 * i) * 64 + c]),
                        __ldg(&Wc2[(kbase + 2 * i + 1) * 64 + c]));
    }
    float b1 = __ldg(&bc1[j]);
    float b2 = __ldg(&bc2[c]);
    float w3 = __ldg(&Wc3[c]);
    float b3 = __ldg(&bc3[0]);

    for (int g = blockIdx.x; g < NN / 4; g += gridDim.x) {
        int base = g * 4;
        // layer 1: emb row = 64 floats = 16 ulonglong2; node stride = 16
        const ulonglong2* er = (const ulonglong2*)(emb + (size_t)base * OUT_C);
        ull a0 = 0, a1 = 0, a2 = 0, a3 = 0;
#pragma unroll
        for (int p = 0; p < 16; p++) {
            ulonglong2 e0 = er[0 * 16 + p], e1 = er[1 * 16 + p];
            ulonglong2 e2 = er[2 * 16 + p], e3 = er[3 * 16 + p];
            ffma2(a0, e0.x, wc1p[2 * p]); ffma2(a0, e0.y, wc1p[2 * p + 1]);
            ffma2(a1, e1.x, wc1p[2 * p]); ffma2(a1, e1.y, wc1p[2 * p + 1]);
            ffma2(a2, e2.x, wc1p[2 * p]); ffma2(a2, e2.y, wc1p[2 * p + 1]);
            ffma2(a3, e3.x, wc1p[2 * p]); ffma2(a3, e3.y, wc1p[2 * p + 1]);
        }
        sc1[0][j] = fmaxf(hadd2(a0) + b1, 0.f);
        sc1[1][j] = fmaxf(hadd2(a1) + b1, 0.f);
        sc1[2][j] = fmaxf(hadd2(a2) + b1, 0.f);
        sc1[3][j] = fmaxf(hadd2(a3) + b1, 0.f);
        __syncthreads();

        // layer 2 partial over k-half (64 values = 16 ulonglong2 from smem)
        ull p0 = 0, p1 = 0, p2 = 0, p3 = 0;
        const ulonglong2* s0 = (const ulonglong2*)(&sc1[0][kbase]);
        const ulonglong2* s1 = (const ulonglong2*)(&sc1[1][kbase]);
        const ulonglong2* s2 = (const ulonglong2*)(&sc1[2][kbase]);
        const ulonglong2* s3 = (const ulonglong2*)(&sc1[3][kbase]);
#pragma unroll
        for (int p = 0; p < 16; p++) {
            ulonglong2 v0 = s0[p], v1 = s1[p], v2 = s2[p], v3 = s3[p];
            ffma2(p0, v0.x, wc2p[2 * p]); ffma2(p0, v0.y, wc2p[2 * p + 1]);
            ffma2(p1, v1.x, wc2p[2 * p]); ffma2(p1, v1.y, wc2p[2 * p + 1]);
            ffma2(p2, v2.x, wc2p[2 * p]); ffma2(p2, v2.y, wc2p[2 * p + 1]);
            ffma2(p3, v3.x, wc2p[2 * p]); ffma2(p3, v3.y, wc2p[2 * p + 1]);
        }
        if (kh == 1) {
            s_p[0][c] = hadd2(p0); s_p[1][c] = hadd2(p1);
            s_p[2][c] = hadd2(p2); s_p[3][c] = hadd2(p3);
        }
        __syncthreads();
        if (kh == 0) {
            float y0 = fmaxf(hadd2(p0) + s_p[0][c] + b2, 0.f) * w3;
            float y1 = fmaxf(hadd2(p1) + s_p[1][c] + b2, 0.f) * w3;
            float y2 = fmaxf(hadd2(p2) + s_p[2][c] + b2, 0.f) * w3;
            float y3 = fmaxf(hadd2(p3) + s_p[3][c] + b2, 0.f) * w3;
#pragma unroll
            for (int off = 16; off; off >>= 1) {
                y0 += __shfl_xor_sync(0xffffffffu, y0, off);
                y1 += __shfl_xor_sync(0xffffffffu, y1, off);
                y2 += __shfl_xor_sync(0xffffffffu, y2, off);
                y3 += __shfl_xor_sync(0xffffffffu, y3, off);
            }
            if ((c & 31) == 0) {
                int w = c >> 5;
                s_red[w][0] = y0; s_red[w][1] = y1;
                s_red[w][2] = y2; s_red[w][3] = y3;
            }
        }
        __syncthreads();
        if (j < 4) {
            float v = s_red[0][j] + s_red[1][j] + b3;
            probs[base + j] = 1.0f / (1.0f + expf(-v));
        }
        __syncthreads();
    }
}

// ---------------- launch ----------------
extern "C" void kernel_launch(void* const* d_in, const int* in_sizes, int n_in,
                              void* d_out, int out_size)
{
    const float* x   = (const float*)d_in[0];
    const void*  ei  = d_in[1];
    const float* Wl1 = (const float*)d_in[2];
    const float* bl1 = (const float*)d_in[3];
    const float* Wr1 = (const float*)d_in[4];
    const float* Wl2 = (const float*)d_in[5];
    const float* bl2 = (const float*)d_in[6];
    const float* Wr2 = (const float*)d_in[7];
    const float* Wc1 = (const float*)d_in[8];
    const float* bc1 = (const float*)d_in[9];
    const float* Wc2 = (const float*)d_in[10];
    const float* bc2 = (const float*)d_in[11];
    const float* Wc3 = (const float*)d_in[12];
    const float* bc3 = (const float*)d_in[13];
    int E = in_sizes[1] / 2;

    float* out   = (float*)d_out;
    float* emb   = out;                          // [NN, 64]
    float* probs = out + (size_t)NN * OUT_C;     // [NN, 1]

    detect_kernel<<<1, 32>>>(ei);
    zero_kernel<<<2048, 256>>>();
    conv1_agg_kernel<<<(E + 15) / 16, 256>>>(x, ei, E);
    conv1_update_kernel<<<444, 128>>>(x, Wl1, bl1, Wr1);
    conv2_agg_kernel<<<(E + 7) / 8, 256>>>(ei, E);
    conv2_update_kernel<<<444, 128>>>(Wl2, bl2, Wr2, emb);
    classifier_kernel<<<444, 128>>>(emb, Wc1, bc1, Wc2, bc2, Wc3, bc3, probs);
}

// round 12
// speedup vs baseline: 1.0935x; 1.0935x over previous
#include <cuda_runtime.h>
#include <math.h>

#define NN    100000
#define IN_C  64
#define HID   128
#define OUT_C 64

typedef unsigned long long ull;

// ---------------- scratch (device globals; no allocation allowed) ----------------
__device__ __align__(16) float g_deg[NN];
__device__ __align__(16) float g_agg1[(size_t)NN * IN_C];   // 25.6 MB
__device__ __align__(16) float g_h[(size_t)NN * HID];       // 51.2 MB
__device__ __align__(16) float g_agg2[(size_t)NN * HID];    // 51.2 MB
__device__ int g_is64;

// transposed weights: [out_ch][k], contiguous per output channel
__device__ __align__(16) float g_Wl1T[HID * IN_C];
__device__ __align__(16) float g_Wr1T[HID * IN_C];
__device__ __align__(16) float g_Wl2T[OUT_C * HID];
__device__ __align__(16) float g_Wr2T[OUT_C * HID];
__device__ __align__(16) float g_Wc1T[HID * OUT_C];
__device__ __align__(16) float g_Wc2T[64 * HID];

// ---------------- packed f32x2 helpers ----------------
__device__ __forceinline__ void ffma2(ull& d, ull a, ull b) {
    asm("fma.rn.f32x2 %0,%1,%2,%0;" : "+l"(d) : "l"(a), "l"(b));
}
__device__ __forceinline__ float hadd2(ull v) {
    float lo, hi; asm("mov.b64 {%0,%1},%2;" : "=f"(lo), "=f"(hi) : "l"(v));
    return lo + hi;
}

// ---------------- fused transpose of all six weight matrices ----------------
// Writes directly into the __device__ globals (no cudaGetSymbolAddress needed).
__global__ void transpose_all_kernel(
    const float* __restrict__ Wl1, const float* __restrict__ Wr1,
    const float* __restrict__ Wl2, const float* __restrict__ Wr2,
    const float* __restrict__ Wc1, const float* __restrict__ Wc2)
{
    int idx = blockIdx.x * blockDim.x + threadIdx.x;
    // segment 0/1: Wl1/Wr1 [IN_C x HID] -> [HID x IN_C]   (8192 each)
    // segment 2/3: Wl2/Wr2 [HID x OUT_C] -> [OUT_C x HID] (8192 each)
    // segment 4:   Wc1 [OUT_C x HID] -> [HID x OUT_C]     (8192)
    // segment 5:   Wc2 [HID x 64] -> [64 x HID]           (8192)
    int seg = idx >> 13;          // 8192 elements per segment
    int t = idx & 8191;
    if (seg == 0) {
        int r = t / HID, c = t % HID;           // r<IN_C, c<HID
        g_Wl1T[c * IN_C + r] = Wl1[t];
    } else if (seg == 1) {
        int r = t / HID, c = t % HID;
        g_Wr1T[c * IN_C + r] = Wr1[t];
    } else if (seg == 2) {
        int r = t / OUT_C, c = t % OUT_C;       // r<HID, c<OUT_C
        g_Wl2T[c * HID + r] = Wl2[t];
    } else if (seg == 3) {
        int r = t / OUT_C, c = t % OUT_C;
        g_Wr2T[c * HID + r] = Wr2[t];
    } else if (seg == 4) {
        int r = t / HID, c = t % HID;           // r<OUT_C, c<HID
        g_Wc1T[c * OUT_C + r] = Wc1[t];
    } else if (seg == 5) {
        int r = t / 64, c = t % 64;             // r<HID, c<64
        g_Wc2T[c * HID + r] = Wc2[t];
    }
}

// ---------------- dtype detect: int64 vs int32 edge_index ----------------
__global__ void detect_kernel(const void* __restrict__ ei) {
    if (blockIdx.x == 0 && threadIdx.x == 0) {
        const unsigned long long* p = (const unsigned long long*)ei;
        int is64 = 1;
#pragma unroll
        for (int i = 0; i < 8; i++)
            if ((p[i] >> 32) != 0ull) is64 = 0;
        g_is64 = is64;
    }
}

// ---------------- zero scratch each launch ----------------
__global__ void zero_kernel() {
    size_t i = (size_t)blockIdx.x * blockDim.x + threadIdx.x;
    size_t stride = (size_t)gridDim.x * blockDim.x;
    float4 z = make_float4(0.f, 0.f, 0.f, 0.f);
    float4* d0 = (float4*)g_deg;
    float4* d1 = (float4*)g_agg1;
    float4* d2 = (float4*)g_agg2;
    for (size_t t = i; t < NN / 4; t += stride) d0[t] = z;
    for (size_t t = i; t < (size_t)NN * IN_C / 4; t += stride) d1[t] = z;
    for (size_t t = i; t < (size_t)NN * HID / 4; t += stride) d2[t] = z;
}

// ---------------- conv1 aggregation: 16 lanes per edge (64 ch) ----------------
__global__ __launch_bounds__(256) void conv1_agg_kernel(
    const float* __restrict__ x, const void* __restrict__ ei, int E)
{
    int tid = blockIdx.x * blockDim.x + threadIdx.x;
    int e = tid >> 4;
    if (e >= E) return;
    int sub = threadIdx.x & 15;
    int is64 = g_is64;
    int src = 0, dst = 0;
    if (sub == 0) {
        if (is64) {
            const long long* p = (const long long*)ei;
            src = (int)p[e]; dst = (int)p[(size_t)E + e];
        } else {
            const int* p = (const int*)ei;
            src = p[e]; dst = p[(size_t)E + e];
        }
    }
    src = __shfl_sync(0xffffffffu, src, 0, 16);
    dst = __shfl_sync(0xffffffffu, dst, 0, 16);

    float4 v = *(const float4*)(x + (size_t)src * IN_C + sub * 4);
    float* d = g_agg1 + (size_t)dst * IN_C + sub * 4;
    asm volatile("red.global.add.v4.f32 [%0], {%1,%2,%3,%4};"
                 :: "l"(d), "f"(v.x), "f"(v.y), "f"(v.z), "f"(v.w) : "memory");
    if (sub == 0) atomicAdd(&g_deg[dst], 1.0f);
}

// ---------------- conv2 aggregation: 32 lanes per edge (128 ch) ----------------
__global__ __launch_bounds__(256) void conv2_agg_kernel(
    const void* __restrict__ ei, int E)
{
    int tid = blockIdx.x * blockDim.x + threadIdx.x;
    int e = tid >> 5;
    if (e >= E) return;
    int ln = threadIdx.x & 31;
    int is64 = g_is64;
    int src = 0, dst = 0;
    if (ln == 0) {
        if (is64) {
            const long long* p = (const long long*)ei;
            src = (int)p[e]; dst = (int)p[(size_t)E + e];
        } else {
            const int* p = (const int*)ei;
            src = p[e]; dst = p[(size_t)E + e];
        }
    }
    src = __shfl_sync(0xffffffffu, src, 0);
    dst = __shfl_sync(0xffffffffu, dst, 0);

    float4 v = *(const float4*)(g_h + (size_t)src * HID + ln * 4);
    float* d = g_agg2 + (size_t)dst * HID + ln * 4;
    asm volatile("red.global.add.v4.f32 [%0], {%1,%2,%3,%4};"
                 :: "l"(d), "f"(v.x), "f"(v.y), "f"(v.z), "f"(v.w) : "memory");
}

// ---------------- conv1 update: h = relu(agg1/deg @ Wl1 + bl1 + x @ Wr1) ----------------
// 128 threads = 128 out channels. Transposed weight rows loaded as ulonglong2
// (L1-resident, shared across CTAs on the SM). 4 nodes per iteration.
__global__ void __launch_bounds__(128, 6) conv1_update_kernel(
    const float* __restrict__ x, const float* __restrict__ bl)
{
    int j = threadIdx.x;                 // out channel 0..127
    const ulonglong2* wlT = (const ulonglong2*)(g_Wl1T + j * IN_C);  // 16 u2
    const ulonglong2* wrT = (const ulonglong2*)(g_Wr1T + j * IN_C);
    float b = __ldg(&bl[j]);

    for (int g = blockIdx.x; g < NN / 4; g += gridDim.x) {
        int base = g * 4;
        const ulonglong2* ag = (const ulonglong2*)(g_agg1 + (size_t)base * IN_C);
        const ulonglong2* xr = (const ulonglong2*)(x + (size_t)base * IN_C);
        ull al0 = 0, al1 = 0, al2 = 0, al3 = 0;
        ull ar0 = 0, ar1 = 0, ar2 = 0, ar3 = 0;
#pragma unroll
        for (int ks = 0; ks < 16; ks++) {           // 4 k per step
            ulonglong2 wl = wlT[ks];
            ulonglong2 wr = wrT[ks];
            ulonglong2 a0 = ag[ks], a1 = ag[16 + ks], a2 = ag[32 + ks], a3 = ag[48 + ks];
            ulonglong2 x0 = xr[ks], x1 = xr[16 + ks], x2 = xr[32 + ks], x3 = xr[48 + ks];
            ffma2(al0, a0.x, wl.x); ffma2(al0, a0.y, wl.y);
            ffma2(al1, a1.x, wl.x); ffma2(al1, a1.y, wl.y);
            ffma2(al2, a2.x, wl.x); ffma2(al2, a2.y, wl.y);
            ffma2(al3, a3.x, wl.x); ffma2(al3, a3.y, wl.y);
            ffma2(ar0, x0.x, wr.x); ffma2(ar0, x0.y, wr.y);
            ffma2(ar1, x1.x, wr.x); ffma2(ar1, x1.y, wr.y);
            ffma2(ar2, x2.x, wr.x); ffma2(ar2, x2.y, wr.y);
            ffma2(ar3, x3.x, wr.x); ffma2(ar3, x3.y, wr.y);
        }
        float d0 = fmaxf(g_deg[base + 0], 1.f);
        float d1 = fmaxf(g_deg[base + 1], 1.f);
        float d2 = fmaxf(g_deg[base + 2], 1.f);
        float d3 = fmaxf(g_deg[base + 3], 1.f);
        g_h[(size_t)(base + 0) * HID + j] = fmaxf(hadd2(al0) / d0 + b + hadd2(ar0), 0.f);
        g_h[(size_t)(base + 1) * HID + j] = fmaxf(hadd2(al1) / d1 + b + hadd2(ar1), 0.f);
        g_h[(size_t)(base + 2) * HID + j] = fmaxf(hadd2(al2) / d2 + b + hadd2(ar2), 0.f);
        g_h[(size_t)(base + 3) * HID + j] = fmaxf(hadd2(al3) / d3 + b + hadd2(ar3), 0.f);
    }
}

// ---------------- conv2 update: emb = agg2/deg @ Wl2 + bl2 + h @ Wr2 ----------------
// 128 threads: thread -> (channel c = tid&63, node-group ng = tid>>6).
// Full K=128 per thread from transposed weight rows; 8 nodes per block iter.
__global__ void __launch_bounds__(128, 6) conv2_update_kernel(
    const float* __restrict__ bl, float* __restrict__ emb)
{
    int c = threadIdx.x & 63;
    int ng = threadIdx.x >> 6;            // 0 or 1
    const ulonglong2* wlT = (const ulonglong2*)(g_Wl2T + c * HID);  // 32 u2
    const ulonglong2* wrT = (const ulonglong2*)(g_Wr2T + c * HID);
    float b = __ldg(&bl[c]);

    for (int g = blockIdx.x; g < NN / 8; g += gridDim.x) {
        int base = g * 8 + ng * 4;
        const ulonglong2* ag = (const ulonglong2*)(g_agg2 + (size_t)base * HID);
        const ulonglong2* hr = (const ulonglong2*)(g_h + (size_t)base * HID);
        ull al0 = 0, al1 = 0, al2 = 0, al3 = 0;
        ull ar0 = 0, ar1 = 0, ar2 = 0, ar3 = 0;
#pragma unroll 8
        for (int ks = 0; ks < 32; ks++) {          // 4 k per step
            ulonglong2 wl = wlT[ks];
            ulonglong2 wr = wrT[ks];
            ulonglong2 a0 = ag[ks], a1 = ag[32 + ks], a2 = ag[64 + ks], a3 = ag[96 + ks];
            ulonglong2 h0 = hr[ks], h1 = hr[32 + ks], h2 = hr[64 + ks], h3 = hr[96 + ks];
            ffma2(al0, a0.x, wl.x); ffma2(al0, a0.y, wl.y);
            ffma2(al1, a1.x, wl.x); ffma2(al1, a1.y, wl.y);
            ffma2(al2, a2.x, wl.x); ffma2(al2, a2.y, wl.y);
            ffma2(al3, a3.x, wl.x); ffma2(al3, a3.y, wl.y);
            ffma2(ar0, h0.x, wr.x); ffma2(ar0, h0.y, wr.y);
            ffma2(ar1, h1.x, wr.x); ffma2(ar1, h1.y, wr.y);
            ffma2(ar2, h2.x, wr.x); ffma2(ar2, h2.y, wr.y);
            ffma2(ar3, h3.x, wr.x); ffma2(ar3, h3.y, wr.y);
        }
        float d0 = fmaxf(g_deg[base + 0], 1.f);
        float d1 = fmaxf(g_deg[base + 1], 1.f);
        float d2 = fmaxf(g_deg[base + 2], 1.f);
        float d3 = fmaxf(g_deg[base + 3], 1.f);
        emb[(size_t)(base + 0) * OUT_C + c] = hadd2(al0) / d0 + b + hadd2(ar0);
        emb[(size_t)(base + 1) * OUT_C + c] = hadd2(al1) / d1 + b + hadd2(ar1);
        emb[(size_t)(base + 2) * OUT_C + c] = hadd2(al2) / d2 + b + hadd2(ar2);
        emb[(size_t)(base + 3) * OUT_C + c] = hadd2(al3) / d3 + b + hadd2(ar3);
    }
}

// ---------------- classifier: sigmoid(relu(relu(emb@Wc1+b)@Wc2+b)@Wc3+b) ----------------
// Layer1: thread j = hidden channel (128), 4 nodes.
// Layer2: thread -> (c = j&63, node-group ng = j>>6 handling 2 nodes), full K=128.
__global__ void __launch_bounds__(128, 6) classifier_kernel(
    const float* __restrict__ emb,
    const float* __restrict__ bc1, const float* __restrict__ bc2,
    const float* __restrict__ Wc3, const float* __restrict__ bc3,
    float* __restrict__ probs)
{
    __shared__ __align__(16) float sc1[4][HID];
    __shared__ float s_red[4][2];
    int j = threadIdx.x;
    int c = j & 63;
    int ng = j >> 6;                       // 0 -> nodes {0,1}, 1 -> nodes {2,3}
    const ulonglong2* w1T = (const ulonglong2*)(g_Wc1T + j * OUT_C);  // 16 u2
    const ulonglong2* w2T = (const ulonglong2*)(g_Wc2T + c * HID);    // 32 u2
    float b1 = __ldg(&bc1[j]);
    float b2 = __ldg(&bc2[c]);
    float w3 = __ldg(&Wc3[c]);
    float b3 = __ldg(&bc3[0]);

    for (int g = blockIdx.x; g < NN / 4; g += gridDim.x) {
        int base = g * 4;
        const ulonglong2* er = (const ulonglong2*)(emb + (size_t)base * OUT_C);
        ull a0 = 0, a1 = 0, a2 = 0, a3 = 0;
#pragma unroll
        for (int p = 0; p < 16; p++) {
            ulonglong2 w = w1T[p];
            ulonglong2 e0 = er[p], e1 = er[16 + p], e2 = er[32 + p], e3 = er[48 + p];
            ffma2(a0, e0.x, w.x); ffma2(a0, e0.y, w.y);
            ffma2(a1, e1.x, w.x); ffma2(a1, e1.y, w.y);
            ffma2(a2, e2.x, w.x); ffma2(a2, e2.y, w.y);
            ffma2(a3, e3.x, w.x); ffma2(a3, e3.y, w.y);
        }
        sc1[0][j] = fmaxf(hadd2(a0) + b1, 0.f);
        sc1[1][j] = fmaxf(hadd2(a1) + b1, 0.f);
        sc1[2][j] = fmaxf(hadd2(a2) + b1, 0.f);
        sc1[3][j] = fmaxf(hadd2(a3) + b1, 0.f);
        __syncthreads();

        // layer 2: two nodes per thread, full K=128 from smem
        ull p0 = 0, p1 = 0;
        const ulonglong2* s0 = (const ulonglong2*)(&sc1[2 * ng][0]);
        const ulonglong2* s1 = (const ulonglong2*)(&sc1[2 * ng + 1][0]);
#pragma unroll
        for (int p = 0; p < 32; p++) {
            ulonglong2 w = w2T[p];
            ulonglong2 v0 = s0[p], v1 = s1[p];
            ffma2(p0, v0.x, w.x); ffma2(p0, v0.y, w.y);
            ffma2(p1, v1.x, w.x); ffma2(p1, v1.y, w.y);
        }
        float y0 = fmaxf(hadd2(p0) + b2, 0.f) * w3;
        float y1 = fmaxf(hadd2(p1) + b2, 0.f) * w3;
#pragma unroll
        for (int off = 16; off; off >>= 1) {
            y0 += __shfl_xor_sync(0xffffffffu, y0, off);
            y1 += __shfl_xor_sync(0xffffffffu, y1, off);
        }
        int wid = j >> 5;                  // warp 0..3
        if ((j & 31) == 0) {
            s_red[wid][0] = y0;
            s_red[wid][1] = y1;
        }
        __syncthreads();
        if (j < 4) {
            int n = j;
            int wb = (n >> 1) * 2;
            float v = s_red[wb][n & 1] + s_red[wb + 1][n & 1] + b3;
            probs[base + n] = 1.0f / (1.0f + expf(-v));
        }
        __syncthreads();
    }
}

// ---------------- launch ----------------
extern "C" void kernel_launch(void* const* d_in, const int* in_sizes, int n_in,
                              void* d_out, int out_size)
{
    const float* x   = (const float*)d_in[0];
    const void*  ei  = d_in[1];
    const float* Wl1 = (const float*)d_in[2];
    const float* bl1 = (const float*)d_in[3];
    const float* Wr1 = (const float*)d_in[4];
    const float* Wl2 = (const float*)d_in[5];
    const float* bl2 = (const float*)d_in[6];
    const float* Wr2 = (const float*)d_in[7];
    const float* Wc1 = (const float*)d_in[8];
    const float* bc1 = (const float*)d_in[9];
    const float* Wc2 = (const float*)d_in[10];
    const float* bc2 = (const float*)d_in[11];
    const float* Wc3 = (const float*)d_in[12];
    const float* bc3 = (const float*)d_in[13];
    int E = in_sizes[1] / 2;

    float* out   = (float*)d_out;
    float* emb   = out;                          // [NN, 64]
    float* probs = out + (size_t)NN * OUT_C;     // [NN, 1]

    detect_kernel<<<1, 32>>>(ei);
    transpose_all_kernel<<<(6 * 8192 + 255) / 256, 256>>>(Wl1, Wr1, Wl2, Wr2, Wc1, Wc2);
    zero_kernel<<<2048, 256>>>();
    conv1_agg_kernel<<<(E + 15) / 16, 256>>>(x, ei, E);
    conv1_update_kernel<<<888, 128>>>(x, bl1);
    conv2_agg_kernel<<<(E + 7) / 8, 256>>>(ei, E);
    conv2_update_kernel<<<888, 128>>>(bl2, emb);
    classifier_kernel<<<888, 128>>>(emb, bc1, bc2, Wc3, bc3, probs);
}

// round 13
// speedup vs baseline: 2.7788x; 2.5413x over previous
#include <cuda_runtime.h>
#include <math.h>

#define NN    100000
#define IN_C  64
#define HID   128
#define OUT_C 64
#define TILE  16

typedef unsigned long long ull;

// ---------------- scratch (device globals; no allocation allowed) ----------------
__device__ __align__(16) float g_deg[NN];
__device__ __align__(16) float g_agg1[(size_t)NN * IN_C];   // 25.6 MB
__device__ __align__(16) float g_h[(size_t)NN * HID];       // 51.2 MB
__device__ __align__(16) float g_agg2[(size_t)NN * HID];    // 51.2 MB
__device__ int g_is64;

// ---------------- packed f32x2 helpers ----------------
__device__ __forceinline__ ull pack2(float lo, float hi) {
    ull r; asm("mov.b64 %0,{%1,%2};" : "=l"(r) : "f"(lo), "f"(hi)); return r;
}
__device__ __forceinline__ void ffma2(ull& d, ull a, ull b) {
    asm("fma.rn.f32x2 %0,%1,%2,%0;" : "+l"(d) : "l"(a), "l"(b));
}
__device__ __forceinline__ float hadd2(ull v) {
    float lo, hi; asm("mov.b64 {%0,%1},%2;" : "=f"(lo), "=f"(hi) : "l"(v));
    return lo + hi;
}

// ---------------- dtype detect: int64 vs int32 edge_index ----------------
__global__ void detect_kernel(const void* __restrict__ ei) {
    if (blockIdx.x == 0 && threadIdx.x == 0) {
        const unsigned long long* p = (const unsigned long long*)ei;
        int is64 = 1;
#pragma unroll
        for (int i = 0; i < 8; i++)
            if ((p[i] >> 32) != 0ull) is64 = 0;
        g_is64 = is64;
    }
}

// ---------------- zero scratch each launch ----------------
__global__ void zero_kernel() {
    size_t i = (size_t)blockIdx.x * blockDim.x + threadIdx.x;
    size_t stride = (size_t)gridDim.x * blockDim.x;
    float4 z = make_float4(0.f, 0.f, 0.f, 0.f);
    float4* d0 = (float4*)g_deg;
    float4* d1 = (float4*)g_agg1;
    float4* d2 = (float4*)g_agg2;
    for (size_t t = i; t < NN / 4; t += stride) d0[t] = z;
    for (size_t t = i; t < (size_t)NN * IN_C / 4; t += stride) d1[t] = z;
    for (size_t t = i; t < (size_t)NN * HID / 4; t += stride) d2[t] = z;
}

// ---------------- conv1 aggregation: 16 lanes per edge (64 ch) ----------------
__global__ __launch_bounds__(256) void conv1_agg_kernel(
    const float* __restrict__ x, const void* __restrict__ ei, int E)
{
    int tid = blockIdx.x * blockDim.x + threadIdx.x;
    int e = tid >> 4;
    if (e >= E) return;
    int sub = threadIdx.x & 15;
    int is64 = g_is64;
    int src = 0, dst = 0;
    if (sub == 0) {
        if (is64) {
            const long long* p = (const long long*)ei;
            src = (int)p[e]; dst = (int)p[(size_t)E + e];
        } else {
            const int* p = (const int*)ei;
            src = p[e]; dst = p[(size_t)E + e];
        }
    }
    src = __shfl_sync(0xffffffffu, src, 0, 16);
    dst = __shfl_sync(0xffffffffu, dst, 0, 16);

    float4 v = *(const float4*)(x + (size_t)src * IN_C + sub * 4);
    float* d = g_agg1 + (size_t)dst * IN_C + sub * 4;
    asm volatile("red.global.add.v4.f32 [%0], {%1,%2,%3,%4};"
                 :: "l"(d), "f"(v.x), "f"(v.y), "f"(v.z), "f"(v.w) : "memory");
    if (sub == 0) atomicAdd(&g_deg[dst], 1.0f);
}

// ---------------- conv2 aggregation: 32 lanes per edge (128 ch) ----------------
__global__ __launch_bounds__(256) void conv2_agg_kernel(
    const void* __restrict__ ei, int E)
{
    int tid = blockIdx.x * blockDim.x + threadIdx.x;
    int e = tid >> 5;
    if (e >= E) return;
    int ln = threadIdx.x & 31;
    int is64 = g_is64;
    int src = 0, dst = 0;
    if (ln == 0) {
        if (is64) {
            const long long* p = (const long long*)ei;
            src = (int)p[e]; dst = (int)p[(size_t)E + e];
        } else {
            const int* p = (const int*)ei;
            src = p[e]; dst = p[(size_t)E + e];
        }
    }
    src = __shfl_sync(0xffffffffu, src, 0);
    dst = __shfl_sync(0xffffffffu, dst, 0);

    float4 v = *(const float4*)(g_h + (size_t)src * HID + ln * 4);
    float* d = g_agg2 + (size_t)dst * HID + ln * 4;
    asm volatile("red.global.add.v4.f32 [%0], {%1,%2,%3,%4};"
                 :: "l"(d), "f"(v.x), "f"(v.y), "f"(v.z), "f"(v.w) : "memory");
}

// ---------------- conv1 update: h = relu(agg1/deg @ Wl1 + bl1 + x @ Wr1) ----------------
// 16-node smem tile staged coalesced once per block: row = [agg/deg | x] (128 floats).
// 128 threads = 128 out channels; weights loaded scalar-coalesced from [k][ch] layout.
__global__ void __launch_bounds__(128, 6) conv1_update_kernel(
    const float* __restrict__ x,
    const float* __restrict__ Wl, const float* __restrict__ bl,
    const float* __restrict__ Wr)
{
    __shared__ __align__(16) float s_in[TILE][2 * IN_C];   // [16][128]
    __shared__ float s_rdeg[TILE];
    int t = threadIdx.x;                 // out channel 0..127
    float b = __ldg(&bl[t]);

    for (int tile = blockIdx.x; tile < NN / TILE; tile += gridDim.x) {
        int base = tile * TILE;
        __syncthreads();                                   // smem reuse guard
        if (t < TILE) s_rdeg[t] = 1.0f / fmaxf(g_deg[base + t], 1.0f);
        __syncthreads();
        // stage 512 float4 (coalesced), 4 per thread
#pragma unroll
        for (int i = 0; i < 4; i++) {
            int f = t + 128 * i;
            int n = f >> 5, q = f & 31;
            if (q < 16) {
                float4 v = *(const float4*)(g_agg1 + (size_t)(base + n) * IN_C + q * 4);
                float r = s_rdeg[n];
                v.x *= r; v.y *= r; v.z *= r; v.w *= r;
                *(float4*)&s_in[n][q * 4] = v;
            } else {
                *(float4*)&s_in[n][q * 4] =
                    __ldg((const float4*)(x + (size_t)(base + n) * IN_C + (q - 16) * 4));
            }
        }
        __syncthreads();

        ull acc[TILE];
#pragma unroll
        for (int n = 0; n < TILE; n++) acc[n] = 0;
        // phase A: (agg/deg) @ Wl  — smem cols 0..63
#pragma unroll 4
        for (int ks = 0; ks < 16; ks++) {
            float w0 = __ldg(&Wl[(4 * ks + 0) * HID + t]);
            float w1 = __ldg(&Wl[(4 * ks + 1) * HID + t]);
            float w2 = __ldg(&Wl[(4 * ks + 2) * HID + t]);
            float w3 = __ldg(&Wl[(4 * ks + 3) * HID + t]);
            ull wA = pack2(w0, w1), wB = pack2(w2, w3);
#pragma unroll
            for (int n = 0; n < TILE; n++) {
                ulonglong2 v = *(const ulonglong2*)&s_in[n][ks * 4];
                ffma2(acc[n], v.x, wA); ffma2(acc[n], v.y, wB);
            }
        }
        // phase B: x @ Wr — smem cols 64..127
#pragma unroll 4
        for (int ks = 0; ks < 16; ks++) {
            float w0 = __ldg(&Wr[(4 * ks + 0) * HID + t]);
            float w1 = __ldg(&Wr[(4 * ks + 1) * HID + t]);
            float w2 = __ldg(&Wr[(4 * ks + 2) * HID + t]);
            float w3 = __ldg(&Wr[(4 * ks + 3) * HID + t]);
            ull wA = pack2(w0, w1), wB = pack2(w2, w3);
#pragma unroll
            for (int n = 0; n < TILE; n++) {
                ulonglong2 v = *(const ulonglong2*)&s_in[n][IN_C + ks * 4];
                ffma2(acc[n], v.x, wA); ffma2(acc[n], v.y, wB);
            }
        }
#pragma unroll
        for (int n = 0; n < TILE; n++)
            g_h[(size_t)(base + n) * HID + t] = fmaxf(hadd2(acc[n]) + b, 0.f);
    }
}

// ---------------- conv2 update: emb = agg2/deg @ Wl2 + bl2 + h @ Wr2 ----------------
// 16-node smem tile, row = [agg2/deg | h] (256 floats).
// 128 threads = 64 channels x 2 node-groups (8 nodes each).
__global__ void __launch_bounds__(128, 6) conv2_update_kernel(
    const float* __restrict__ Wl, const float* __restrict__ bl,
    const float* __restrict__ Wr, float* __restrict__ emb)
{
    __shared__ __align__(16) float s_in[TILE][2 * HID];    // [16][256] = 16 KB
    __shared__ float s_rdeg[TILE];
    int t = threadIdx.x;
    int c = t & 63;
    int nb = (t >> 6) * 8;
    float b = __ldg(&bl[c]);

    for (int tile = blockIdx.x; tile < NN / TILE; tile += gridDim.x) {
        int base = tile * TILE;
        __syncthreads();
        if (t < TILE) s_rdeg[t] = 1.0f / fmaxf(g_deg[base + t], 1.0f);
        __syncthreads();
        // stage 1024 float4, 8 per thread
#pragma unroll
        for (int i = 0; i < 8; i++) {
            int f = t + 128 * i;
            int n = f >> 6, q = f & 63;
            if (q < 32) {
                float4 v = *(const float4*)(g_agg2 + (size_t)(base + n) * HID + q * 4);
                float r = s_rdeg[n];
                v.x *= r; v.y *= r; v.z *= r; v.w *= r;
                *(float4*)&s_in[n][q * 4] = v;
            } else {
                *(float4*)&s_in[n][q * 4] =
                    *(const float4*)(g_h + (size_t)(base + n) * HID + (q - 32) * 4);
            }
        }
        __syncthreads();

        ull acc[8];
#pragma unroll
        for (int n = 0; n < 8; n++) acc[n] = 0;
        // phase A: (agg2/deg) @ Wl2 — smem cols 0..127
#pragma unroll 4
        for (int ks = 0; ks < 32; ks++) {
            float w0 = __ldg(&Wl[(4 * ks + 0) * OUT_C + c]);
            float w1 = __ldg(&Wl[(4 * ks + 1) * OUT_C + c]);
            float w2 = __ldg(&Wl[(4 * ks + 2) * OUT_C + c]);
            float w3 = __ldg(&Wl[(4 * ks + 3) * OUT_C + c]);
            ull wA = pack2(w0, w1), wB = pack2(w2, w3);
#pragma unroll
            for (int n = 0; n < 8; n++) {
                ulonglong2 v = *(const ulonglong2*)&s_in[nb + n][ks * 4];
                ffma2(acc[n], v.x, wA); ffma2(acc[n], v.y, wB);
            }
        }
        // phase B: h @ Wr2 — smem cols 128..255
#pragma unroll 4
        for (int ks = 0; ks < 32; ks++) {
            float w0 = __ldg(&Wr[(4 * ks + 0) * OUT_C + c]);
            float w1 = __ldg(&Wr[(4 * ks + 1) * OUT_C + c]);
            float w2 = __ldg(&Wr[(4 * ks + 2) * OUT_C + c]);
            float w3 = __ldg(&Wr[(4 * ks + 3) * OUT_C + c]);
            ull wA = pack2(w0, w1), wB = pack2(w2, w3);
#pragma unroll
            for (int n = 0; n < 8; n++) {
                ulonglong2 v = *(const ulonglong2*)&s_in[nb + n][HID + ks * 4];
                ffma2(acc[n], v.x, wA); ffma2(acc[n], v.y, wB);
            }
        }
#pragma unroll
        for (int n = 0; n < 8; n++)
            emb[(size_t)(base + nb + n) * OUT_C + c] = hadd2(acc[n]) + b;
    }
}

// ---------------- classifier: sigmoid(relu(relu(emb@Wc1+b)@Wc2+b)@Wc3+b) ----------------
// 16-node tile. L1: 128 threads = 128 hidden ch. L2+L3: 64 ch x 2 node-groups,
// warp-shuffle channel reduction, sigmoid on 16 lanes.
__global__ void __launch_bounds__(128, 6) classifier_kernel(
    const float* __restrict__ emb,
    const float* __restrict__ Wc1, const float* __restrict__ bc1,
    const float* __restrict__ Wc2, const float* __restrict__ bc2,
    const float* __restrict__ Wc3, const float* __restrict__ bc3,
    float* __restrict__ probs)
{
    __shared__ __align__(16) float s_e[TILE][OUT_C];       // 4 KB
    __shared__ __align__(16) float s_c1[TILE][HID];        // 8 KB
    __shared__ float s_part[4][8];
    int t = threadIdx.x;
    int c = t & 63;
    int nb = (t >> 6) * 8;
    int wid = t >> 5;
    float b1 = __ldg(&bc1[t]);
    float b2 = __ldg(&bc2[c]);
    float w3c = __ldg(&Wc3[c]);
    float b3 = __ldg(&bc3[0]);

    for (int tile = blockIdx.x; tile < NN / TILE; tile += gridDim.x) {
        int base = tile * TILE;
        __syncthreads();
        // stage emb tile: 256 float4, 2 per thread
#pragma unroll
        for (int i = 0; i < 2; i++) {
            int f = t + 128 * i;
            int n = f >> 4, q = f & 15;
            *(float4*)&s_e[n][q * 4] =
                *(const float4*)(emb + (size_t)(base + n) * OUT_C + q * 4);
        }
        __syncthreads();

        // layer 1: c1 = relu(emb @ Wc1 + b1), thread t = hidden channel
        {
            ull acc[TILE];
#pragma unroll
            for (int n = 0; n < TILE; n++) acc[n] = 0;
#pragma unroll 4
            for (int ks = 0; ks < 16; ks++) {
                float w0 = __ldg(&Wc1[(4 * ks + 0) * HID + t]);
                float w1 = __ldg(&Wc1[(4 * ks + 1) * HID + t]);
                float w2 = __ldg(&Wc1[(4 * ks + 2) * HID + t]);
                float w3 = __ldg(&Wc1[(4 * ks + 3) * HID + t]);
                ull wA = pack2(w0, w1), wB = pack2(w2, w3);
#pragma unroll
                for (int n = 0; n < TILE; n++) {
                    ulonglong2 v = *(const ulonglong2*)&s_e[n][ks * 4];
                    ffma2(acc[n], v.x, wA); ffma2(acc[n], v.y, wB);
                }
            }
#pragma unroll
            for (int n = 0; n < TILE; n++)
                s_c1[n][t] = fmaxf(hadd2(acc[n]) + b1, 0.f);
        }
        __syncthreads();

        // layer 2 + 3: thread (c, node-group), 8 nodes
        {
            ull p[8];
#pragma unroll
            for (int n = 0; n < 8; n++) p[n] = 0;
#pragma unroll 4
            for (int ks = 0; ks < 32; ks++) {
                float w0 = __ldg(&Wc2[(4 * ks + 0) * 64 + c]);
                float w1 = __ldg(&Wc2[(4 * ks + 1) * 64 + c]);
                float w2 = __ldg(&Wc2[(4 * ks + 2) * 64 + c]);
                float w3 = __ldg(&Wc2[(4 * ks + 3) * 64 + c]);
                ull wA = pack2(w0, w1), wB = pack2(w2, w3);
#pragma unroll
                for (int n = 0; n < 8; n++) {
                    ulonglong2 v = *(const ulonglong2*)&s_c1[nb + n][ks * 4];
                    ffma2(p[n], v.x, wA); ffma2(p[n], v.y, wB);
                }
            }
            float y[8];
#pragma unroll
            for (int n = 0; n < 8; n++)
                y[n] = fmaxf(hadd2(p[n]) + b2, 0.f) * w3c;
#pragma unroll
            for (int off = 16; off; off >>= 1) {
#pragma unroll
                for (int n = 0; n < 8; n++)
                    y[n] += __shfl_xor_sync(0xffffffffu, y[n], off);
            }
            if ((t & 31) == 0) {
#pragma unroll
                for (int n = 0; n < 8; n++) s_part[wid][n] = y[n];
            }
        }
        __syncthreads();
        if (t < TILE) {
            int n = t;
            float v = (n < 8) ? (s_part[0][n] + s_part[1][n])
                              : (s_part[2][n - 8] + s_part[3][n - 8]);
            v += b3;
            probs[base + n] = 1.0f / (1.0f + expf(-v));
        }
    }
}

// ---------------- launch ----------------
extern "C" void kernel_launch(void* const* d_in, const int* in_sizes, int n_in,
                              void* d_out, int out_size)
{
    const float* x   = (const float*)d_in[0];
    const void*  ei  = d_in[1];
    const float* Wl1 = (const float*)d_in[2];
    const float* bl1 = (const float*)d_in[3];
    const float* Wr1 = (const float*)d_in[4];
    const float* Wl2 = (const float*)d_in[5];
    const float* bl2 = (const float*)d_in[6];
    const float* Wr2 = (const float*)d_in[7];
    const float* Wc1 = (const float*)d_in[8];
    const float* bc1 = (const float*)d_in[9];
    const float* Wc2 = (const float*)d_in[10];
    const float* bc2 = (const float*)d_in[11];
    const float* Wc3 = (const float*)d_in[12];
    const float* bc3 = (const float*)d_in[13];
    int E = in_sizes[1] / 2;

    float* out   = (float*)d_out;
    float* emb   = out;                          // [NN, 64]
    float* probs = out + (size_t)NN * OUT_C;     // [NN, 1]

    detect_kernel<<<1, 32>>>(ei);
    zero_kernel<<<2048, 256>>>();
    conv1_agg_kernel<<<(E + 15) / 16, 256>>>(x, ei, E);
    conv1_update_kernel<<<888, 128>>>(x, Wl1, bl1, Wr1);
    conv2_agg_kernel<<<(E + 7) / 8, 256>>>(ei, E);
    conv2_update_kernel<<<888, 128>>>(Wl2, bl2, Wr2, emb);
    classifier_kernel<<<888, 128>>>(emb, Wc1, bc1, Wc2, bc2, Wc3, bc3, probs);
}